// round 6
// baseline (speedup 1.0000x reference)
#include <cuda_runtime.h>
#include <cuda_bf16.h>
#include <stdint.h>

// Problem constants (fixed by the dataset)
#define NN 100000      // nodes
#define NE 1600000     // edges
#define NF 256         // input features
#define NH 128         // hidden
#define NC 40          // classes

// ---------------- Scratch (static __device__, no allocations) ----------------
__device__ float g_h1[(size_t)NN * NH];   // GEMM output / agg input
__device__ float g_ha[(size_t)NN * NH];   // agg output / next GEMM input
__device__ int   g_csr[NE];               // CSR src list grouped by dst
__device__ int   g_deg[NN];
__device__ int   g_off[NN];
__device__ int   g_cur[NN];
__device__ float g_dinv[NN];
__device__ int   g_bsum[128];
__device__ int   g_boff[128];
__device__ int   g_e64;                   // 1 if edge_index is int64, 0 if int32

__device__ __forceinline__ float* scratch_buf(int sel) {
    return (sel == 0) ? g_h1 : g_ha;
}

// Edge load honoring detected dtype. idx is in ELEMENTS of the stored dtype.
__device__ __forceinline__ int load_edge(const void* ei, long long idx) {
    if (g_e64) return (int)((const long long*)ei)[idx];
    return ((const int*)ei)[idx];
}

// ---------------- dtype probe ----------------
// JAX silently downgrades int64->int32 when x64 is disabled (the default), so
// the buffer may be int32 despite the reference saying int64. Reading an int32
// buffer as int64 yields values with random nonzero high words -> out of range.
__global__ void k_detect_dtype(const long long* __restrict__ ei) {
    __shared__ int ok64;
    if (threadIdx.x == 0) ok64 = 1;
    __syncthreads();
    for (int i = threadIdx.x; i < 2048; i += blockDim.x) {
        long long v = ei[i];
        if (v < 0 || v >= (long long)NN) ok64 = 0;  // benign race, all write 0
    }
    __syncthreads();
    if (threadIdx.x == 0) g_e64 = ok64;
}

// ---------------- Degree + CSR build ----------------
__global__ void k_zero_deg(int n) {
    int gid = blockIdx.x * blockDim.x + threadIdx.x;
    if (gid < n) g_deg[gid] = 0;
}

__global__ void k_count_deg(const void* __restrict__ ei, int E) {
    int e = blockIdx.x * blockDim.x + threadIdx.x;
    if (e < E) {
        int d = load_edge(ei, (long long)E + e);
        if (d >= 0 && d < NN) atomicAdd(&g_deg[d], 1);
    }
}

// Block-level exclusive scan of g_deg into g_off; also dinv = rsqrt(deg+1)
__global__ void k_scan_blocks(int n) {
    int tid = threadIdx.x;
    int gid = blockIdx.x * 1024 + tid;
    int lane = tid & 31, wid = tid >> 5;
    int v = (gid < n) ? g_deg[gid] : 0;
    int x = v;
#pragma unroll
    for (int d = 1; d < 32; d <<= 1) {
        int y = __shfl_up_sync(0xffffffffu, x, d);
        if (lane >= d) x += y;
    }
    __shared__ int ws[32];
    if (lane == 31) ws[wid] = x;
    __syncthreads();
    if (wid == 0) {
        int w = ws[lane];
        int t = w;
#pragma unroll
        for (int d = 1; d < 32; d <<= 1) {
            int y = __shfl_up_sync(0xffffffffu, t, d);
            if (lane >= d) t += y;
        }
        ws[lane] = t - w;  // exclusive warp offsets
    }
    __syncthreads();
    int excl = ws[wid] + x - v;
    if (gid < n) {
        g_off[gid] = excl;
        g_dinv[gid] = rsqrtf((float)v + 1.0f);
    }
    if (tid == 1023) g_bsum[blockIdx.x] = excl + v;  // block total
}

__global__ void k_scan_sums(int nb) {
    int tid = threadIdx.x, lane = tid & 31, wid = tid >> 5;
    int v = (tid < nb) ? g_bsum[tid] : 0;
    int x = v;
#pragma unroll
    for (int d = 1; d < 32; d <<= 1) {
        int y = __shfl_up_sync(0xffffffffu, x, d);
        if (lane >= d) x += y;
    }
    __shared__ int ws[4];
    if (lane == 31) ws[wid] = x;
    __syncthreads();
    if (tid == 0) {
        int a = 0;
#pragma unroll
        for (int i = 0; i < 4; i++) { int t = ws[i]; ws[i] = a; a += t; }
    }
    __syncthreads();
    int excl = ws[wid] + x - v;
    if (tid < nb) g_boff[tid] = excl;
}

__global__ void k_scan_add(int n) {
    int gid = blockIdx.x * 1024 + threadIdx.x;
    if (gid < n) {
        int o = g_off[gid] + g_boff[blockIdx.x];
        g_off[gid] = o;
        g_cur[gid] = o;
    }
}

__global__ void k_fill_csr(const void* __restrict__ ei, int E) {
    int e = blockIdx.x * blockDim.x + threadIdx.x;
    if (e < E) {
        int s = load_edge(ei, e);
        int d = load_edge(ei, (long long)E + e);
        if (s >= 0 && s < NN && d >= 0 && d < NN) {
            int p = atomicAdd(&g_cur[d], 1);
            g_csr[p] = s;
        }
    }
}

// ---------------- Tiled SGEMM: C[M,N] = A[M,K] @ B[K,N] (+bias) ----------------
// asel/csel: 0 -> g_h1, 1 -> g_ha, negative -> use the external pointer arg.
template <int BM, int BN, int BK, int TM, int TN>
__global__ void sgemm(const float* __restrict__ Aext, int asel,
                      const float* __restrict__ B,
                      float* __restrict__ Cext, int csel,
                      const float* __restrict__ bias,
                      int M, int N, int K) {
    const float* A = (asel < 0) ? Aext : scratch_buf(asel);
    float*       C = (csel < 0) ? Cext : scratch_buf(csel);

    constexpr int THREADS = (BM / TM) * (BN / TN);
    __shared__ float As[BK][BM + 1];
    __shared__ float Bs[BK][BN];

    const int block_row = blockIdx.y * BM;
    const int tid = threadIdx.x;
    const int tcol = tid % (BN / TN);
    const int trow = tid / (BN / TN);

    float acc[TM][TN];
#pragma unroll
    for (int i = 0; i < TM; i++)
#pragma unroll
        for (int j = 0; j < TN; j++) acc[i][j] = 0.0f;

    for (int k0 = 0; k0 < K; k0 += BK) {
        // Load A tile (BM x BK), transposed into As[k][m]
        for (int i = tid * 4; i < BM * BK; i += THREADS * 4) {
            int r = i / BK, c = i % BK;
            int row = block_row + r;
            float4 v = make_float4(0.f, 0.f, 0.f, 0.f);
            if (row < M) v = *(const float4*)(A + (size_t)row * K + k0 + c);
            As[c + 0][r] = v.x;
            As[c + 1][r] = v.y;
            As[c + 2][r] = v.z;
            As[c + 3][r] = v.w;
        }
        // Load B tile (BK x BN)
        for (int i = tid * 4; i < BK * BN; i += THREADS * 4) {
            int r = i / BN, c = i % BN;
            *(float4*)&Bs[r][c] = *(const float4*)(B + (size_t)(k0 + r) * N + c);
        }
        __syncthreads();

#pragma unroll
        for (int k = 0; k < BK; k++) {
            float ra[TM], rb[TN];
#pragma unroll
            for (int i = 0; i < TM; i++) ra[i] = As[k][trow * TM + i];
#pragma unroll
            for (int j = 0; j < TN; j++) rb[j] = Bs[k][tcol * TN + j];
#pragma unroll
            for (int i = 0; i < TM; i++)
#pragma unroll
                for (int j = 0; j < TN; j++) acc[i][j] += ra[i] * rb[j];
        }
        __syncthreads();
    }

#pragma unroll
    for (int i = 0; i < TM; i++) {
        int row = block_row + trow * TM + i;
        if (row < M) {
#pragma unroll
            for (int j = 0; j < TN; j++) {
                int col = tcol * TN + j;
                float v = acc[i][j];
                if (bias) v += bias[col];
                C[(size_t)row * N + col] = v;
            }
        }
    }
}

// ---------------- Fused aggregation: warp per node ----------------
// out[i] = relu( sum_{j in N(i)} dinv[j]*dinv[i]*h[j] + dinv[i]^2 * h[i] + bias )
__global__ void k_aggregate(int hsel, const float* __restrict__ bias,
                            int osel, int n_nodes) {
    const float* __restrict__ h = scratch_buf(hsel);
    float* __restrict__ out = scratch_buf(osel);

    int warp = (blockIdx.x * blockDim.x + threadIdx.x) >> 5;
    if (warp >= n_nodes) return;
    int lane = threadIdx.x & 31;
    int node = warp;

    float dd = g_dinv[node];
    int start = g_off[node];
    int cnt = g_deg[node];

    // self-loop contribution
    float4 acc = *(const float4*)(h + (size_t)node * NH + lane * 4);
    float sw = dd * dd;
    acc.x *= sw; acc.y *= sw; acc.z *= sw; acc.w *= sw;

    for (int j = 0; j < cnt; j++) {
        int s = g_csr[start + j];       // uniform within warp -> broadcast
        float w = g_dinv[s] * dd;
        float4 v = *(const float4*)(h + (size_t)s * NH + lane * 4);
        acc.x += v.x * w;
        acc.y += v.y * w;
        acc.z += v.z * w;
        acc.w += v.w * w;
    }

    int c = lane * 4;
    acc.x = fmaxf(acc.x + bias[c + 0], 0.0f);
    acc.y = fmaxf(acc.y + bias[c + 1], 0.0f);
    acc.z = fmaxf(acc.z + bias[c + 2], 0.0f);
    acc.w = fmaxf(acc.w + bias[c + 3], 0.0f);
    *(float4*)(out + (size_t)node * NH + c) = acc;
}

// ---------------- Launch ----------------
extern "C" void kernel_launch(void* const* d_in, const int* in_sizes, int n_in,
                              void* d_out, int out_size) {
    const float* x       = (const float*)d_in[0];
    const void*  ei      = d_in[1];             // dtype detected on device
    const float* W1      = (const float*)d_in[2];
    const float* b1      = (const float*)d_in[3];
    const float* W2      = (const float*)d_in[4];
    const float* b2      = (const float*)d_in[5];
    const float* Wc      = (const float*)d_in[6];
    const float* bc      = (const float*)d_in[7];
    float* out           = (float*)d_out;

    const int N = in_sizes[0] / NF;       // 100000
    const int E = in_sizes[1] / 2;        // 1600000
    const int nb = (N + 1023) / 1024;

    // CSR build
    k_detect_dtype<<<1, 256>>>((const long long*)ei);
    k_zero_deg<<<(N + 1023) / 1024, 1024>>>(N);
    k_count_deg<<<(E + 255) / 256, 256>>>(ei, E);
    k_scan_blocks<<<nb, 1024>>>(N);
    k_scan_sums<<<1, 128>>>(nb);
    k_scan_add<<<nb, 1024>>>(N);
    k_fill_csr<<<(E + 255) / 256, 256>>>(ei, E);

    const int agg_blocks = (int)(((long long)N * 32 + 255) / 256);

    // Layer 1: g_h1 = x @ W1 ; aggregate -> g_ha
    {
        dim3 grid(1, (N + 63) / 64);
        sgemm<64, 128, 32, 4, 8><<<grid, 256>>>(x, -1, W1, nullptr, 0, nullptr,
                                                N, NH, NF);
    }
    k_aggregate<<<agg_blocks, 256>>>(0, b1, 1, N);

    // Layer 2: g_h1 = g_ha @ W2 ; aggregate -> g_ha
    {
        dim3 grid(1, (N + 63) / 64);
        sgemm<64, 128, 32, 4, 8><<<grid, 256>>>(nullptr, 1, W2, nullptr, 0, nullptr,
                                                N, NH, NH);
    }
    k_aggregate<<<agg_blocks, 256>>>(0, b2, 1, N);

    // Classifier: out = g_ha @ Wc + bc
    {
        dim3 grid(1, (N + 127) / 128);
        sgemm<128, 40, 32, 4, 8><<<grid, 160>>>(nullptr, 1, Wc, out, -1, bc,
                                                N, NC, NH);
    }
}

// round 7
// speedup vs baseline: 1.1188x; 1.1188x over previous
#include <cuda_runtime.h>
#include <cuda_bf16.h>
#include <stdint.h>

// Problem constants (fixed by the dataset)
#define NN 100000      // nodes
#define NE 1600000     // edges
#define NF 256         // input features
#define NH 128         // hidden
#define NC 40          // classes

// ---------------- Scratch (static __device__, no allocations) ----------------
__device__ float g_h1[(size_t)NN * NH];   // GEMM output / agg input
__device__ float g_ha[(size_t)NN * NH];   // agg output / next GEMM input
__device__ int   g_csr[NE];               // CSR src list grouped by dst
__device__ int   g_deg[NN];
__device__ int   g_off[NN];
__device__ int   g_cur[NN];
__device__ float g_dinv[NN];
__device__ int   g_bsum[128];
__device__ int   g_boff[128];
__device__ int   g_e64;                   // 1 if edge_index is int64, 0 if int32

__device__ __forceinline__ float* scratch_buf(int sel) {
    return (sel == 0) ? g_h1 : g_ha;
}

// Edge load honoring detected dtype. idx is in ELEMENTS of the stored dtype.
__device__ __forceinline__ int load_edge(const void* ei, long long idx) {
    if (g_e64) return (int)((const long long*)ei)[idx];
    return ((const int*)ei)[idx];
}

// ---------------- dtype probe ----------------
// JAX silently downgrades int64->int32 when x64 is disabled (the default).
__global__ void k_detect_dtype(const long long* __restrict__ ei) {
    __shared__ int ok64;
    if (threadIdx.x == 0) ok64 = 1;
    __syncthreads();
    for (int i = threadIdx.x; i < 2048; i += blockDim.x) {
        long long v = ei[i];
        if (v < 0 || v >= (long long)NN) ok64 = 0;
    }
    __syncthreads();
    if (threadIdx.x == 0) g_e64 = ok64;
}

// ---------------- Degree + CSR build ----------------
__global__ void k_zero_deg(int n) {
    int gid = blockIdx.x * blockDim.x + threadIdx.x;
    if (gid < n) g_deg[gid] = 0;
}

__global__ void k_count_deg(const void* __restrict__ ei, int E) {
    int e = blockIdx.x * blockDim.x + threadIdx.x;
    if (e < E) {
        int d = load_edge(ei, (long long)E + e);
        if (d >= 0 && d < NN) atomicAdd(&g_deg[d], 1);
    }
}

// Block-level exclusive scan of g_deg into g_off; also dinv = rsqrt(deg+1)
__global__ void k_scan_blocks(int n) {
    int tid = threadIdx.x;
    int gid = blockIdx.x * 1024 + tid;
    int lane = tid & 31, wid = tid >> 5;
    int v = (gid < n) ? g_deg[gid] : 0;
    int x = v;
#pragma unroll
    for (int d = 1; d < 32; d <<= 1) {
        int y = __shfl_up_sync(0xffffffffu, x, d);
        if (lane >= d) x += y;
    }
    __shared__ int ws[32];
    if (lane == 31) ws[wid] = x;
    __syncthreads();
    if (wid == 0) {
        int w = ws[lane];
        int t = w;
#pragma unroll
        for (int d = 1; d < 32; d <<= 1) {
            int y = __shfl_up_sync(0xffffffffu, t, d);
            if (lane >= d) t += y;
        }
        ws[lane] = t - w;  // exclusive warp offsets
    }
    __syncthreads();
    int excl = ws[wid] + x - v;
    if (gid < n) {
        g_off[gid] = excl;
        g_dinv[gid] = rsqrtf((float)v + 1.0f);
    }
    if (tid == 1023) g_bsum[blockIdx.x] = excl + v;  // block total
}

__global__ void k_scan_sums(int nb) {
    int tid = threadIdx.x, lane = tid & 31, wid = tid >> 5;
    int v = (tid < nb) ? g_bsum[tid] : 0;
    int x = v;
#pragma unroll
    for (int d = 1; d < 32; d <<= 1) {
        int y = __shfl_up_sync(0xffffffffu, x, d);
        if (lane >= d) x += y;
    }
    __shared__ int ws[4];
    if (lane == 31) ws[wid] = x;
    __syncthreads();
    if (tid == 0) {
        int a = 0;
#pragma unroll
        for (int i = 0; i < 4; i++) { int t = ws[i]; ws[i] = a; a += t; }
    }
    __syncthreads();
    int excl = ws[wid] + x - v;
    if (tid < nb) g_boff[tid] = excl;
}

__global__ void k_scan_add(int n) {
    int gid = blockIdx.x * 1024 + threadIdx.x;
    if (gid < n) {
        int o = g_off[gid] + g_boff[blockIdx.x];
        g_off[gid] = o;
        g_cur[gid] = o;
    }
}

__global__ void k_fill_csr(const void* __restrict__ ei, int E) {
    int e = blockIdx.x * blockDim.x + threadIdx.x;
    if (e < E) {
        int s = load_edge(ei, e);
        int d = load_edge(ei, (long long)E + e);
        if (s >= 0 && s < NN && d >= 0 && d < NN) {
            int p = atomicAdd(&g_cur[d], 1);
            g_csr[p] = s;
        }
    }
}

// ---------------- Tiled SGEMM: C[M,N] = A[M,K] @ B[K,N] (+bias) ----------------
// asel/csel: 0 -> g_h1, 1 -> g_ha, negative -> use the external pointer arg.
// scale_dinv: multiply each output row by g_dinv[row] in the epilogue.
template <int BM, int BN, int BK, int TM, int TN, bool SCALE_DINV>
__global__ void sgemm(const float* __restrict__ Aext, int asel,
                      const float* __restrict__ B,
                      float* __restrict__ Cext, int csel,
                      const float* __restrict__ bias,
                      int M, int N, int K) {
    const float* A = (asel < 0) ? Aext : scratch_buf(asel);
    float*       C = (csel < 0) ? Cext : scratch_buf(csel);

    constexpr int THREADS = (BM / TM) * (BN / TN);
    __shared__ float As[BK][BM + 1];
    __shared__ float Bs[BK][BN];

    const int block_row = blockIdx.y * BM;
    const int tid = threadIdx.x;
    const int tcol = tid % (BN / TN);
    const int trow = tid / (BN / TN);

    float acc[TM][TN];
#pragma unroll
    for (int i = 0; i < TM; i++)
#pragma unroll
        for (int j = 0; j < TN; j++) acc[i][j] = 0.0f;

    for (int k0 = 0; k0 < K; k0 += BK) {
        // Load A tile (BM x BK), transposed into As[k][m]
        for (int i = tid * 4; i < BM * BK; i += THREADS * 4) {
            int r = i / BK, c = i % BK;
            int row = block_row + r;
            float4 v = make_float4(0.f, 0.f, 0.f, 0.f);
            if (row < M) v = *(const float4*)(A + (size_t)row * K + k0 + c);
            As[c + 0][r] = v.x;
            As[c + 1][r] = v.y;
            As[c + 2][r] = v.z;
            As[c + 3][r] = v.w;
        }
        // Load B tile (BK x BN)
        for (int i = tid * 4; i < BK * BN; i += THREADS * 4) {
            int r = i / BN, c = i % BN;
            *(float4*)&Bs[r][c] = *(const float4*)(B + (size_t)(k0 + r) * N + c);
        }
        __syncthreads();

#pragma unroll
        for (int k = 0; k < BK; k++) {
            float ra[TM], rb[TN];
#pragma unroll
            for (int i = 0; i < TM; i++) ra[i] = As[k][trow * TM + i];
#pragma unroll
            for (int j = 0; j < TN; j++) rb[j] = Bs[k][tcol * TN + j];
#pragma unroll
            for (int i = 0; i < TM; i++)
#pragma unroll
                for (int j = 0; j < TN; j++) acc[i][j] += ra[i] * rb[j];
        }
        __syncthreads();
    }

#pragma unroll
    for (int i = 0; i < TM; i++) {
        int row = block_row + trow * TM + i;
        if (row < M) {
            float scale = SCALE_DINV ? g_dinv[row] : 1.0f;
#pragma unroll
            for (int j = 0; j < TN; j++) {
                int col = tcol * TN + j;
                float v = acc[i][j] * scale;
                if (bias) v += bias[col];
                C[(size_t)row * N + col] = v;
            }
        }
    }
}

// ---------------- Fused aggregation: warp per node ----------------
// Input h is PRE-SCALED: hn[i] = dinv[i] * (X@W)[i].
// out[i] = relu( dinv[i] * ( hn[i] + sum_{j in N(i)} hn[j] ) + bias )
__global__ void k_aggregate(int hsel, const float* __restrict__ bias,
                            int osel, int n_nodes) {
    const float* __restrict__ h = scratch_buf(hsel);
    float* __restrict__ out = scratch_buf(osel);

    int warp = (blockIdx.x * blockDim.x + threadIdx.x) >> 5;
    if (warp >= n_nodes) return;
    int lane = threadIdx.x & 31;
    int node = warp;

    float dd = g_dinv[node];
    int start = g_off[node];
    int cnt = g_deg[node];

    const float* hb = h + (size_t)lane * 4;   // lane's 16B slice base

    // self-loop contribution: dd * hn[node]  (accumulated pre-scale)
    float4 acc = *(const float4*)(hb + (size_t)node * NH);

    int j = 0;
    // 4x unroll: 4 independent float4 gathers in flight per warp
    for (; j + 4 <= cnt; j += 4) {
        int s0 = g_csr[start + j + 0];
        int s1 = g_csr[start + j + 1];
        int s2 = g_csr[start + j + 2];
        int s3 = g_csr[start + j + 3];
        float4 v0 = *(const float4*)(hb + (size_t)s0 * NH);
        float4 v1 = *(const float4*)(hb + (size_t)s1 * NH);
        float4 v2 = *(const float4*)(hb + (size_t)s2 * NH);
        float4 v3 = *(const float4*)(hb + (size_t)s3 * NH);
        acc.x += (v0.x + v1.x) + (v2.x + v3.x);
        acc.y += (v0.y + v1.y) + (v2.y + v3.y);
        acc.z += (v0.z + v1.z) + (v2.z + v3.z);
        acc.w += (v0.w + v1.w) + (v2.w + v3.w);
    }
    for (; j < cnt; j++) {
        int s = g_csr[start + j];
        float4 v = *(const float4*)(hb + (size_t)s * NH);
        acc.x += v.x; acc.y += v.y; acc.z += v.z; acc.w += v.w;
    }

    int c = lane * 4;
    acc.x = fmaxf(fmaf(acc.x, dd, bias[c + 0]), 0.0f);
    acc.y = fmaxf(fmaf(acc.y, dd, bias[c + 1]), 0.0f);
    acc.z = fmaxf(fmaf(acc.z, dd, bias[c + 2]), 0.0f);
    acc.w = fmaxf(fmaf(acc.w, dd, bias[c + 3]), 0.0f);
    *(float4*)(out + (size_t)node * NH + c) = acc;
}

// ---------------- Launch ----------------
extern "C" void kernel_launch(void* const* d_in, const int* in_sizes, int n_in,
                              void* d_out, int out_size) {
    const float* x       = (const float*)d_in[0];
    const void*  ei      = d_in[1];             // dtype detected on device
    const float* W1      = (const float*)d_in[2];
    const float* b1      = (const float*)d_in[3];
    const float* W2      = (const float*)d_in[4];
    const float* b2      = (const float*)d_in[5];
    const float* Wc      = (const float*)d_in[6];
    const float* bc      = (const float*)d_in[7];
    float* out           = (float*)d_out;

    const int N = in_sizes[0] / NF;       // 100000
    const int E = in_sizes[1] / 2;        // 1600000
    const int nb = (N + 1023) / 1024;

    // CSR build (also produces g_dinv, needed by the GEMM epilogue)
    k_detect_dtype<<<1, 256>>>((const long long*)ei);
    k_zero_deg<<<(N + 1023) / 1024, 1024>>>(N);
    k_count_deg<<<(E + 511) / 512, 512>>>(ei, E);
    k_scan_blocks<<<nb, 1024>>>(N);
    k_scan_sums<<<1, 128>>>(nb);
    k_scan_add<<<nb, 1024>>>(N);
    k_fill_csr<<<(E + 511) / 512, 512>>>(ei, E);

    const int agg_blocks = (int)(((long long)N * 32 + 255) / 256);

    // Layer 1: g_h1 = dinv * (x @ W1) ; aggregate -> g_ha
    {
        dim3 grid(1, (N + 127) / 128);
        sgemm<128, 128, 16, 8, 8, true><<<grid, 256>>>(x, -1, W1, nullptr, 0,
                                                       nullptr, N, NH, NF);
    }
    k_aggregate<<<agg_blocks, 256>>>(0, b1, 1, N);

    // Layer 2: g_h1 = dinv * (g_ha @ W2) ; aggregate -> g_ha
    {
        dim3 grid(1, (N + 127) / 128);
        sgemm<128, 128, 16, 8, 8, true><<<grid, 256>>>(nullptr, 1, W2, nullptr, 0,
                                                       nullptr, N, NH, NH);
    }
    k_aggregate<<<agg_blocks, 256>>>(0, b2, 1, N);

    // Classifier: out = g_ha @ Wc + bc
    {
        dim3 grid(1, (N + 127) / 128);
        sgemm<128, 40, 32, 4, 8, false><<<grid, 160>>>(nullptr, 1, Wc, out, -1,
                                                       bc, N, NC, NH);
    }
}

// round 10
// speedup vs baseline: 1.3092x; 1.1702x over previous
#include <cuda_runtime.h>
#include <cuda_bf16.h>
#include <stdint.h>

// Problem constants (fixed by the dataset)
#define NN 100000      // nodes
#define NE 1600000     // edges
#define NF 256         // input features
#define NH 128         // hidden
#define NC 40          // classes

// ---------------- Scratch (static __device__, no allocations) ----------------
__device__ float g_h1[(size_t)NN * NH];   // GEMM output / agg input
__device__ float g_ha[(size_t)NN * NH];   // agg output / next GEMM input
__device__ int   g_csr[NE];               // CSR src list grouped by dst
__device__ int   g_deg[NN];
__device__ int   g_off[NN];
__device__ int   g_cur[NN];
__device__ float g_dinv[NN];
__device__ int   g_bsum[128];
__device__ int   g_boff[128];
__device__ int   g_e64;                   // 1 if edge_index is int64, 0 if int32

__device__ __forceinline__ float* scratch_buf(int sel) {
    return (sel == 0) ? g_h1 : g_ha;
}

// Edge load honoring detected dtype.
__device__ __forceinline__ int load_edge(const void* ei, long long idx) {
    if (g_e64) return (int)((const long long*)ei)[idx];
    return ((const int*)ei)[idx];
}

// Packed f32x2 helpers (Blackwell base ISA, no 'a' suffix needed)
#define FMA_F32X2(d, a, b) \
    asm("fma.rn.f32x2 %0, %1, %2, %3;" : "=l"(d) : "l"(a), "l"(b), "l"(d))
#define PACK_DUP(out, x) \
    asm("mov.b64 %0, {%1, %1};" : "=l"(out) : "f"(x))
#define UNPACK2(lo, hi, in) \
    asm("mov.b64 {%0, %1}, %2;" : "=f"(lo), "=f"(hi) : "l"(in))

// ---------------- dtype probe ----------------
// JAX silently downgrades int64->int32 when x64 is disabled (the default).
__global__ void k_detect_dtype(const long long* __restrict__ ei) {
    __shared__ int ok64;
    if (threadIdx.x == 0) ok64 = 1;
    __syncthreads();
    for (int i = threadIdx.x; i < 2048; i += blockDim.x) {
        long long v = ei[i];
        if (v < 0 || v >= (long long)NN) ok64 = 0;
    }
    __syncthreads();
    if (threadIdx.x == 0) g_e64 = ok64;
}

// ---------------- Degree + CSR build ----------------
__global__ void k_zero_deg(int n) {
    int gid = blockIdx.x * blockDim.x + threadIdx.x;
    if (gid < n) g_deg[gid] = 0;
}

__global__ void k_count_deg(const void* __restrict__ ei, int E) {
    int e = blockIdx.x * blockDim.x + threadIdx.x;
    if (e < E) {
        int d = load_edge(ei, (long long)E + e);
        if (d >= 0 && d < NN) atomicAdd(&g_deg[d], 1);
    }
}

__global__ void k_scan_blocks(int n) {
    int tid = threadIdx.x;
    int gid = blockIdx.x * 1024 + tid;
    int lane = tid & 31, wid = tid >> 5;
    int v = (gid < n) ? g_deg[gid] : 0;
    int x = v;
#pragma unroll
    for (int d = 1; d < 32; d <<= 1) {
        int y = __shfl_up_sync(0xffffffffu, x, d);
        if (lane >= d) x += y;
    }
    __shared__ int ws[32];
    if (lane == 31) ws[wid] = x;
    __syncthreads();
    if (wid == 0) {
        int w = ws[lane];
        int t = w;
#pragma unroll
        for (int d = 1; d < 32; d <<= 1) {
            int y = __shfl_up_sync(0xffffffffu, t, d);
            if (lane >= d) t += y;
        }
        ws[lane] = t - w;
    }
    __syncthreads();
    int excl = ws[wid] + x - v;
    if (gid < n) {
        g_off[gid] = excl;
        g_dinv[gid] = rsqrtf((float)v + 1.0f);
    }
    if (tid == 1023) g_bsum[blockIdx.x] = excl + v;
}

__global__ void k_scan_sums(int nb) {
    int tid = threadIdx.x, lane = tid & 31, wid = tid >> 5;
    int v = (tid < nb) ? g_bsum[tid] : 0;
    int x = v;
#pragma unroll
    for (int d = 1; d < 32; d <<= 1) {
        int y = __shfl_up_sync(0xffffffffu, x, d);
        if (lane >= d) x += y;
    }
    __shared__ int ws[4];
    if (lane == 31) ws[wid] = x;
    __syncthreads();
    if (tid == 0) {
        int a = 0;
#pragma unroll
        for (int i = 0; i < 4; i++) { int t = ws[i]; ws[i] = a; a += t; }
    }
    __syncthreads();
    int excl = ws[wid] + x - v;
    if (tid < nb) g_boff[tid] = excl;
}

__global__ void k_scan_add(int n) {
    int gid = blockIdx.x * 1024 + threadIdx.x;
    if (gid < n) {
        int o = g_off[gid] + g_boff[blockIdx.x];
        g_off[gid] = o;
        g_cur[gid] = o;
    }
}

__global__ void k_fill_csr(const void* __restrict__ ei, int E) {
    int e = blockIdx.x * blockDim.x + threadIdx.x;
    if (e < E) {
        int s = load_edge(ei, e);
        int d = load_edge(ei, (long long)E + e);
        if (s >= 0 && s < NN && d >= 0 && d < NN) {
            int p = atomicAdd(&g_cur[d], 1);
            g_csr[p] = s;
        }
    }
}

// ------- f32x2 SGEMM (layers 1-2): C[M,128] = dinv[row] * (A[M,K] @ B[K,128]) -
// BM=128, BN=128, BK=16, TM=8, TN=8, 256 threads. Uses packed fma.rn.f32x2:
// accumulators hold column pairs; A broadcast-packed, B pairs loaded as 8B LDS.
template <int BK>
__global__ void __launch_bounds__(256)
sgemm2(const float* __restrict__ Aext, int asel,
       const float* __restrict__ B, int csel, int M, int K) {
    constexpr int BM = 128, BN = 128, TM = 8, TN = 8;
    constexpr int THREADS = 256;

    const float* A = (asel < 0) ? Aext : scratch_buf(asel);
    float* C = scratch_buf(csel);

    __shared__ __align__(16) float As[BK][BM + 2];
    __shared__ __align__(16) float Bs[BK][BN];

    const int block_row = blockIdx.y * BM;
    const int tid = threadIdx.x;
    const int tcol = tid % (BN / TN);   // 0..15
    const int trow = tid / (BN / TN);   // 0..15

    unsigned long long acc[TM][TN / 2];
#pragma unroll
    for (int i = 0; i < TM; i++)
#pragma unroll
        for (int j = 0; j < TN / 2; j++) acc[i][j] = 0ull;

    for (int k0 = 0; k0 < K; k0 += BK) {
        // Load A tile (BM x BK), transposed into As[k][m]
#pragma unroll
        for (int i = tid * 4; i < BM * BK; i += THREADS * 4) {
            int r = i / BK, c = i % BK;
            int row = block_row + r;
            float4 v = make_float4(0.f, 0.f, 0.f, 0.f);
            if (row < M) v = *(const float4*)(A + (size_t)row * K + k0 + c);
            As[c + 0][r] = v.x;
            As[c + 1][r] = v.y;
            As[c + 2][r] = v.z;
            As[c + 3][r] = v.w;
        }
        // Load B tile (BK x BN)
#pragma unroll
        for (int i = tid * 4; i < BK * BN; i += THREADS * 4) {
            int r = i / BN, c = i % BN;
            *(float4*)&Bs[r][c] = *(const float4*)(B + (size_t)(k0 + r) * BN + c);
        }
        __syncthreads();

#pragma unroll
        for (int k = 0; k < BK; k++) {
            unsigned long long a2[TM], b2[TN / 2];
#pragma unroll
            for (int i = 0; i < TM; i++) {
                float ra = As[k][trow * TM + i];
                PACK_DUP(a2[i], ra);
            }
#pragma unroll
            for (int j = 0; j < TN / 2; j++)
                b2[j] = *(const unsigned long long*)&Bs[k][tcol * TN + 2 * j];
#pragma unroll
            for (int i = 0; i < TM; i++)
#pragma unroll
                for (int j = 0; j < TN / 2; j++)
                    FMA_F32X2(acc[i][j], a2[i], b2[j]);
        }
        __syncthreads();
    }

    // Epilogue: scale by dinv[row], store
#pragma unroll
    for (int i = 0; i < TM; i++) {
        int row = block_row + trow * TM + i;
        if (row < M) {
            float scale = g_dinv[row];
            float* crow = C + (size_t)row * NH + tcol * TN;
#pragma unroll
            for (int j = 0; j < TN / 2; j += 2) {
                float4 v;
                UNPACK2(v.x, v.y, acc[i][j]);
                UNPACK2(v.z, v.w, acc[i][j + 1]);
                v.x *= scale; v.y *= scale; v.z *= scale; v.w *= scale;
                *(float4*)(crow + 2 * j) = v;
            }
        }
    }
}

// ---------------- Tiled SGEMM (classifier) ----------------
template <int BM, int BN, int BK, int TM, int TN>
__global__ void sgemm(int asel, const float* __restrict__ B,
                      float* __restrict__ Cext,
                      const float* __restrict__ bias,
                      int M, int N, int K) {
    const float* A = scratch_buf(asel);
    float*       C = Cext;

    constexpr int THREADS = (BM / TM) * (BN / TN);
    __shared__ float As[BK][BM + 1];
    __shared__ float Bs[BK][BN];

    const int block_row = blockIdx.y * BM;
    const int tid = threadIdx.x;
    const int tcol = tid % (BN / TN);
    const int trow = tid / (BN / TN);

    float acc[TM][TN];
#pragma unroll
    for (int i = 0; i < TM; i++)
#pragma unroll
        for (int j = 0; j < TN; j++) acc[i][j] = 0.0f;

    for (int k0 = 0; k0 < K; k0 += BK) {
        for (int i = tid * 4; i < BM * BK; i += THREADS * 4) {
            int r = i / BK, c = i % BK;
            int row = block_row + r;
            float4 v = make_float4(0.f, 0.f, 0.f, 0.f);
            if (row < M) v = *(const float4*)(A + (size_t)row * K + k0 + c);
            As[c + 0][r] = v.x;
            As[c + 1][r] = v.y;
            As[c + 2][r] = v.z;
            As[c + 3][r] = v.w;
        }
        for (int i = tid * 4; i < BK * BN; i += THREADS * 4) {
            int r = i / BN, c = i % BN;
            *(float4*)&Bs[r][c] = *(const float4*)(B + (size_t)(k0 + r) * N + c);
        }
        __syncthreads();

#pragma unroll
        for (int k = 0; k < BK; k++) {
            float ra[TM], rb[TN];
#pragma unroll
            for (int i = 0; i < TM; i++) ra[i] = As[k][trow * TM + i];
#pragma unroll
            for (int j = 0; j < TN; j++) rb[j] = Bs[k][tcol * TN + j];
#pragma unroll
            for (int i = 0; i < TM; i++)
#pragma unroll
                for (int j = 0; j < TN; j++) acc[i][j] += ra[i] * rb[j];
        }
        __syncthreads();
    }

#pragma unroll
    for (int i = 0; i < TM; i++) {
        int row = block_row + trow * TM + i;
        if (row < M) {
#pragma unroll
            for (int j = 0; j < TN; j++) {
                int col = tcol * TN + j;
                C[(size_t)row * N + col] = acc[i][j] + bias[col];
            }
        }
    }
}

// ---------------- Fused aggregation: warp per node ----------------
// Input h is PRE-SCALED: hn[i] = dinv[i] * (X@W)[i].
// out[i] = relu( dinv[i] * ( hn[i] + sum_{j in N(i)} hn[j] ) + bias )
__global__ void k_aggregate(int hsel, const float* __restrict__ bias,
                            int osel, int n_nodes) {
    const float* __restrict__ h = scratch_buf(hsel);
    float* __restrict__ out = scratch_buf(osel);

    int warp = (blockIdx.x * blockDim.x + threadIdx.x) >> 5;
    if (warp >= n_nodes) return;
    int lane = threadIdx.x & 31;
    int node = warp;

    float dd = g_dinv[node];
    int start = g_off[node];
    int cnt = g_deg[node];

    const float* hb = h + (size_t)lane * 4;

    float4 acc = *(const float4*)(hb + (size_t)node * NH);

    int j = 0;
    for (; j + 4 <= cnt; j += 4) {
        int s0 = g_csr[start + j + 0];
        int s1 = g_csr[start + j + 1];
        int s2 = g_csr[start + j + 2];
        int s3 = g_csr[start + j + 3];
        float4 v0 = *(const float4*)(hb + (size_t)s0 * NH);
        float4 v1 = *(const float4*)(hb + (size_t)s1 * NH);
        float4 v2 = *(const float4*)(hb + (size_t)s2 * NH);
        float4 v3 = *(const float4*)(hb + (size_t)s3 * NH);
        acc.x += (v0.x + v1.x) + (v2.x + v3.x);
        acc.y += (v0.y + v1.y) + (v2.y + v3.y);
        acc.z += (v0.z + v1.z) + (v2.z + v3.z);
        acc.w += (v0.w + v1.w) + (v2.w + v3.w);
    }
    for (; j < cnt; j++) {
        int s = g_csr[start + j];
        float4 v = *(const float4*)(hb + (size_t)s * NH);
        acc.x += v.x; acc.y += v.y; acc.z += v.z; acc.w += v.w;
    }

    int c = lane * 4;
    acc.x = fmaxf(fmaf(acc.x, dd, bias[c + 0]), 0.0f);
    acc.y = fmaxf(fmaf(acc.y, dd, bias[c + 1]), 0.0f);
    acc.z = fmaxf(fmaf(acc.z, dd, bias[c + 2]), 0.0f);
    acc.w = fmaxf(fmaf(acc.w, dd, bias[c + 3]), 0.0f);
    *(float4*)(out + (size_t)node * NH + c) = acc;
}

// ---------------- Launch ----------------
extern "C" void kernel_launch(void* const* d_in, const int* in_sizes, int n_in,
                              void* d_out, int out_size) {
    const float* x       = (const float*)d_in[0];
    const void*  ei      = d_in[1];
    const float* W1      = (const float*)d_in[2];
    const float* b1      = (const float*)d_in[3];
    const float* W2      = (const float*)d_in[4];
    const float* b2      = (const float*)d_in[5];
    const float* Wc      = (const float*)d_in[6];
    const float* bc      = (const float*)d_in[7];
    float* out           = (float*)d_out;

    const int N = in_sizes[0] / NF;       // 100000
    const int E = in_sizes[1] / 2;        // 1600000
    const int nb = (N + 1023) / 1024;

    // CSR build (produces g_dinv needed by GEMM epilogues)
    k_detect_dtype<<<1, 256>>>((const long long*)ei);
    k_zero_deg<<<(N + 1023) / 1024, 1024>>>(N);
    k_count_deg<<<(E + 511) / 512, 512>>>(ei, E);
    k_scan_blocks<<<nb, 1024>>>(N);
    k_scan_sums<<<1, 128>>>(nb);
    k_scan_add<<<nb, 1024>>>(N);
    k_fill_csr<<<(E + 511) / 512, 512>>>(ei, E);

    const int agg_blocks = (int)(((long long)N * 32 + 255) / 256);

    // Layer 1: g_h1 = dinv * (x @ W1) ; aggregate -> g_ha
    {
        dim3 grid(1, (N + 127) / 128);
        sgemm2<16><<<grid, 256>>>(x, -1, W1, 0, N, NF);
    }
    k_aggregate<<<agg_blocks, 256>>>(0, b1, 1, N);

    // Layer 2: g_h1 = dinv * (g_ha @ W2) ; aggregate -> g_ha
    {
        dim3 grid(1, (N + 127) / 128);
        sgemm2<16><<<grid, 256>>>(nullptr, 1, W2, 0, N, NH);
    }
    k_aggregate<<<agg_blocks, 256>>>(0, b2, 1, N);

    // Classifier: out = g_ha @ Wc + bc   (SIMT, small)
    {
        dim3 grid(1, (N + 127) / 128);
        sgemm<128, 40, 32, 4, 8><<<grid, 160>>>(1, Wc, out, bc, N, NC, NH);
    }
}